// round 14
// baseline (speedup 1.0000x reference)
#include <cuda_runtime.h>
#include <cuda_fp16.h>
#include <cuda.h>
#include <math.h>

#define BATCH 256
#define HID   1024
#define H3    3072
#define VOC   512
#define TT    256
#define FPD   2048
#define WH    (H3 * HID)
#define NB    128

// ---------------- device scratch ----------------
__device__ __align__(256) float  g_h0[2][BATCH * HID];
__device__ __align__(256) float  g_h1[2][BATCH * HID];
__device__ __align__(256) __half g_h0h[2][BATCH * HID];
__device__ __align__(256) __half g_h1h[2][BATCH * HID];
__device__ __align__(256) float  g_G0[VOC * H3];
__device__ __align__(256) __half g_Whh_h[2][WH];
__device__ __align__(256) __half g_Wih1_h[WH];
__device__ __align__(256) __half g_Wo_h[VOC * HID];
__device__ __align__(256) __half g_Hbufh[(size_t)TT * BATCH * HID];
__device__ unsigned g_bar_cnt4[4] = {0, 0, 0, 0};
__device__ unsigned g_bar_gen4[4] = {0, 0, 0, 0};

// ---------------- helpers ----------------
__device__ __forceinline__ unsigned f2tf(float f) {
    unsigned u; asm("cvt.rna.tf32.f32 %0, %1;" : "=r"(u) : "f"(f)); return u;
}
__device__ __forceinline__ void mma8(float c[4], const unsigned a[4], const unsigned b[2]) {
    asm volatile("mma.sync.aligned.m16n8k8.row.col.f32.tf32.tf32.f32 "
                 "{%0,%1,%2,%3},{%4,%5,%6,%7},{%8,%9},{%0,%1,%2,%3};"
                 : "+f"(c[0]), "+f"(c[1]), "+f"(c[2]), "+f"(c[3])
                 : "r"(a[0]), "r"(a[1]), "r"(a[2]), "r"(a[3]), "r"(b[0]), "r"(b[1]));
}
__device__ __forceinline__ void mmah(float c[4], const unsigned a[4], const unsigned b[2]) {
    asm volatile("mma.sync.aligned.m16n8k16.row.col.f32.f16.f16.f32 "
                 "{%0,%1,%2,%3},{%4,%5,%6,%7},{%8,%9},{%0,%1,%2,%3};"
                 : "+f"(c[0]), "+f"(c[1]), "+f"(c[2]), "+f"(c[3])
                 : "r"(a[0]), "r"(a[1]), "r"(a[2]), "r"(a[3]), "r"(b[0]), "r"(b[1]));
}
__device__ __forceinline__ void ldsm4u(unsigned r[4], unsigned a) {
    asm volatile("ldmatrix.sync.aligned.m8n8.x4.shared.b16 {%0,%1,%2,%3},[%4];"
                 : "=r"(r[0]), "=r"(r[1]), "=r"(r[2]), "=r"(r[3]) : "r"(a));
}
__device__ __forceinline__ void ldsm2u(unsigned r[2], unsigned a) {
    asm volatile("ldmatrix.sync.aligned.m8n8.x2.shared.b16 {%0,%1},[%2];"
                 : "=r"(r[0]), "=r"(r[1]) : "r"(a));
}
__device__ __forceinline__ void ldsm4h(unsigned r[4], const __half* p) {
    ldsm4u(r, (unsigned)__cvta_generic_to_shared(p));
}
__device__ __forceinline__ float sigm(float x) { return 1.0f / (1.0f + __expf(-x)); }
__device__ __forceinline__ void cpa16(const __half* dst, const __half* src) {
    unsigned d = (unsigned)__cvta_generic_to_shared(dst);
    asm volatile("cp.async.cg.shared.global [%0], [%1], 16;" :: "r"(d), "l"(src));
}
__device__ __forceinline__ void cpcommit() { asm volatile("cp.async.commit_group;"); }
__device__ __forceinline__ void cpwait1()  { asm volatile("cp.async.wait_group 1;"); }
__device__ __forceinline__ void cpwait0()  { asm volatile("cp.async.wait_group 0;"); }
__device__ __forceinline__ unsigned swz(unsigned o) { return o ^ ((o >> 3) & 0x70); }

#define MB_INIT(addr, cnt) asm volatile("mbarrier.init.shared.b64 [%0], %1;" :: "r"(addr), "r"(cnt) : "memory")
#define MB_EXPECT(addr, bytes) asm volatile("mbarrier.arrive.expect_tx.shared.b64 _, [%0], %1;" :: "r"(addr), "r"(bytes) : "memory")
#define MB_ARRIVE(addr) asm volatile("mbarrier.arrive.shared.b64 _, [%0];" :: "r"(addr) : "memory")
#define MB_WAIT(addr, par) do { \
    unsigned _m = (addr); unsigned _p = (par); unsigned _d; \
    asm volatile("{\n\t.reg .pred p;\n\tmbarrier.try_wait.parity.acquire.cta.shared::cta.b64 p, [%1], %2;\n\tselp.b32 %0, 1, 0, p;\n\t}" \
        : "=r"(_d) : "r"(_m), "r"(_p) : "memory"); \
    if (!_d) { \
        asm volatile("{\n\t.reg .pred P1;\n\tWL_%=:\n\tmbarrier.try_wait.parity.acquire.cta.shared::cta.b64 P1, [%0], %1, 0x989680;\n\t@P1 bra.uni WD_%=;\n\tbra.uni WL_%=;\n\tWD_%=:\n\t}" \
            :: "r"(_m), "r"(_p) : "memory"); \
    } \
} while (0)

__device__ __forceinline__ void tma3(unsigned dst, const CUtensorMap* m, int x, int y, int z, unsigned mb) {
    asm volatile("cp.async.bulk.tensor.3d.shared::cta.global.tile.mbarrier::complete_tx::bytes "
                 "[%0], [%1, {%2,%3,%4}], [%5];"
                 :: "r"(dst), "l"(m), "r"(x), "r"(y), "r"(z), "r"(mb) : "memory");
}

// 32-CTA m-group barrier (groups are independent)
__device__ __forceinline__ void gbarrier_grp(int grp) {
    __threadfence();
    __syncthreads();
    if (threadIdx.x == 0) {
        unsigned gen = *((volatile unsigned*)&g_bar_gen4[grp]);
        if (atomicAdd(&g_bar_cnt4[grp], 1u) == 31u) {
            g_bar_cnt4[grp] = 0;
            __threadfence();
            atomicAdd(&g_bar_gen4[grp], 1u);
        } else {
            while (*((volatile unsigned*)&g_bar_gen4[grp]) == gen) { __nanosleep(16); }
        }
    }
    __syncthreads();
}

// ---------------- tf32 64x64 GEMM (init kernels only) ----------------
__device__ __forceinline__ void gemm64x64(const float* A, int lda, const float* W, int ldw,
                                          int K, int m0, int n0, int reluA,
                                          unsigned* As, unsigned* Bs, float c[2][2][4]) {
    const int tid = threadIdx.x, lane = tid & 31, wid = tid >> 5;
    const int g = lane >> 2, t4 = lane & 3;
    const int warpM = wid >> 2, warpN = wid & 3;
    for (int kk = 0; kk < K; kk += 32) {
#pragma unroll
        for (int p = 0; p < 2; p++) {
            int r = p * 32 + (tid >> 3), c4 = (tid & 7) * 4;
            float4 v = *(const float4*)(A + (size_t)(m0 + r) * lda + kk + c4);
            if (reluA) { v.x = fmaxf(v.x, 0.f); v.y = fmaxf(v.y, 0.f); v.z = fmaxf(v.z, 0.f); v.w = fmaxf(v.w, 0.f); }
            unsigned* d = As + r * 36 + c4;
            d[0] = f2tf(v.x); d[1] = f2tf(v.y); d[2] = f2tf(v.z); d[3] = f2tf(v.w);
            float4 w = *(const float4*)(W + (size_t)(n0 + r) * ldw + kk + c4);
            unsigned* e = Bs + r * 36 + c4;
            e[0] = f2tf(w.x); e[1] = f2tf(w.y); e[2] = f2tf(w.z); e[3] = f2tf(w.w);
        }
        __syncthreads();
#pragma unroll
        for (int ks = 0; ks < 4; ks++) {
            int kb = ks * 8;
            unsigned a[2][4], b[2][2];
#pragma unroll
            for (int mt = 0; mt < 2; mt++) {
                int row = warpM * 32 + mt * 16 + g;
                a[mt][0] = As[row * 36 + kb + t4];
                a[mt][1] = As[(row + 8) * 36 + kb + t4];
                a[mt][2] = As[row * 36 + kb + t4 + 4];
                a[mt][3] = As[(row + 8) * 36 + kb + t4 + 4];
            }
#pragma unroll
            for (int nt = 0; nt < 2; nt++) {
                int nr = warpN * 16 + nt * 8 + g;
                b[nt][0] = Bs[nr * 36 + kb + t4];
                b[nt][1] = Bs[nr * 36 + kb + t4 + 4];
            }
#pragma unroll
            for (int mt = 0; mt < 2; mt++)
#pragma unroll
                for (int nt = 0; nt < 2; nt++) mma8(c[mt][nt], a[mt], b[nt]);
        }
        __syncthreads();
    }
}

__global__ __launch_bounds__(256) void k_init_h0(const float* fp, const float* Wc, const float* bc) {
    __shared__ unsigned As[64 * 36], Bs[64 * 36];
    float c[2][2][4] = {};
    int n0 = blockIdx.x * 64, m0 = blockIdx.y * 64;
    gemm64x64(fp, FPD, Wc, FPD, FPD, m0, n0, 0, As, Bs, c);
    const int tid = threadIdx.x, lane = tid & 31, wid = tid >> 5;
    const int g = lane >> 2, t4 = lane & 3;
    const int warpM = wid >> 2, warpN = wid & 3;
#pragma unroll
    for (int mt = 0; mt < 2; mt++)
#pragma unroll
        for (int nt = 0; nt < 2; nt++)
#pragma unroll
            for (int ci = 0; ci < 4; ci++) {
                int m = m0 + warpM * 32 + mt * 16 + g + ((ci & 2) ? 8 : 0);
                int n = n0 + warpN * 16 + nt * 8 + t4 * 2 + (ci & 1);
                float v = fmaxf(c[mt][nt][ci] + bc[n], 0.f);
                g_h0[0][m * HID + n] = v;
                g_h1[0][m * HID + n] = v;
                __half vh = __float2half_rn(v);
                g_h0h[0][m * HID + n] = vh;
                g_h1h[0][m * HID + n] = vh;
                g_h1h[1][m * HID + n] = vh;
            }
}

__global__ __launch_bounds__(256) void k_init_G0(const float* emb, const float* Wih, const float* bih) {
    __shared__ unsigned As[64 * 36], Bs[64 * 36];
    float c[2][2][4] = {};
    int n0 = blockIdx.x * 64, m0 = blockIdx.y * 64;
    gemm64x64(emb, HID, Wih, HID, HID, m0, n0, 1, As, Bs, c);
    const int tid = threadIdx.x, lane = tid & 31, wid = tid >> 5;
    const int g = lane >> 2, t4 = lane & 3;
    const int warpM = wid >> 2, warpN = wid & 3;
#pragma unroll
    for (int mt = 0; mt < 2; mt++)
#pragma unroll
        for (int nt = 0; nt < 2; nt++)
#pragma unroll
            for (int ci = 0; ci < 4; ci++) {
                int m = m0 + warpM * 32 + mt * 16 + g + ((ci & 2) ? 8 : 0);
                int n = n0 + warpN * 16 + nt * 8 + t4 * 2 + (ci & 1);
                g_G0[m * H3 + n] = c[mt][nt][ci] + bih[n];
            }
}

__global__ __launch_bounds__(256) void k_convW(const float* Whh, const float* Wih, const float* Wo) {
    size_t i = (size_t)blockIdx.x * blockDim.x + threadIdx.x;
    size_t stride = (size_t)gridDim.x * blockDim.x;
    __half* whh = &g_Whh_h[0][0];
    for (size_t k = i; k < 2 * (size_t)WH; k += stride) whh[k] = __float2half_rn(Whh[k]);
    for (size_t k = i; k < (size_t)WH; k += stride) g_Wih1_h[k] = __float2half_rn(Wih[WH + k]);
    for (size_t k = i; k < (size_t)VOC * HID; k += stride) g_Wo_h[k] = __float2half_rn(Wo[k]);
}

// ---------------- persistent recurrent kernel (v12: split W/A issue across tick boundary) ----------------
// Tick k (k=0..TT): A(k): gh0 = h0(k-1)@Whh0 -> h0(k)   [skip at k=TT]
//                   B(k-1): gh1 = h1(k-2)@Whh1, gi1 = h0(k-1)@Wih1, fuse -> h1(k-1) [skip at k=0]
// CTA tile: 64m x (3 gates x 32j); 4 m-tiles x 32 j-tiles = 128 CTAs. 16 warps = 4M x 4J, warp 16m x 8j.
// Full barrier arrive count = 2: W issue (k-independent coords, may cross the tick barrier) + A issue.
#define STG_BYTES 53248   // h0 8K + h1 8K + 9 W boxes x 4K
#define NSTG 4
#define KLOOP_SMEM (NSTG * STG_BYTES)

__global__ __launch_bounds__(512, 1)
void k_loop(const int* __restrict__ tgt, const float* __restrict__ b_ih, const float* __restrict__ b_hh,
            const __grid_constant__ CUtensorMap mWhh, const __grid_constant__ CUtensorMap mWih1,
            const __grid_constant__ CUtensorMap mH0,  const __grid_constant__ CUtensorMap mH1)
{
    extern __shared__ __align__(1024) char dynsm[];
    __shared__ __align__(8) unsigned long long s_mbar[2 * NSTG];
    const unsigned smb = (unsigned)__cvta_generic_to_shared(dynsm);
    const unsigned mbb = (unsigned)__cvta_generic_to_shared(s_mbar);
#define mbF(s)  (mbb + (s) * 8)
#define mbE(s)  (mbb + NSTG * 8 + (s) * 8)
#define stg(s)  (smb + (s) * STG_BYTES)

    const int tid = threadIdx.x, lane = tid & 31, wid = tid >> 5;
    const int g8 = lane >> 2, t4 = lane & 3;
    const int warpM = wid & 3, warpJ = wid >> 2;      // 4M x 4J
    const int bid = blockIdx.x;
    const int grp = bid >> 5;                          // m-group (32 CTAs share m0)
    const int m0 = grp * 64;
    const int jb = (bid & 31) * 32;
    const float* bh0 = b_hh;
    const float* bh1 = b_hh + H3;
    const float* bi1 = b_ih + H3;

    if (tid == 0) {
#pragma unroll
        for (int s = 0; s < NSTG; s++) { MB_INIT(mbF(s), 2); MB_INIT(mbE(s), 16); }
    }
    __syncthreads();

    // register-resident hidden state for this thread's epilogue positions
    float hA[4], hB[4];
#pragma unroll
    for (int ci2 = 0; ci2 < 2; ci2++) {
        int m = m0 + warpM * 16 + g8 + ci2 * 8;
#pragma unroll
        for (int e = 0; e < 2; e++) {
            int j = jb + warpJ * 8 + t4 * 2 + e;
            hA[ci2 * 2 + e] = g_h0[0][m * HID + j];
            hB[ci2 * 2 + e] = g_h1[0][m * HID + j];
        }
    }

    // ldmatrix lane addressing (offsets within swizzled 128B-row boxes)
    const int l15 = lane & 15;
    const unsigned hiA = (lane >> 4) * 16;
    const unsigned rA  = (unsigned)(warpM * 16 + l15) * 128;        // 16m warp tile
    const unsigned rB  = (unsigned)(warpJ * 8 + (l15 & 7)) * 128;
    const unsigned hiB = ((l15 >> 3) & 1) * 16;

// W issue: waits stage-empty, posts W tx (36864 B), 9 boxes; coordinates are k-independent.
#define ISSW(X, CK) do { \
    unsigned s_ = (unsigned)(X) & 3; \
    MB_WAIT(mbE(s_), ((((unsigned)(X)) >> 2) & 1u) ^ 1u); \
    MB_EXPECT(mbF(s_), 36864u); \
    _Pragma("unroll") for (int g_ = 0; g_ < 3; g_++) { \
        tma3(stg(s_) + 16384u + g_ * 4096u, &mWhh,  (CK) * 64, g_ * HID + jb, 0, mbF(s_)); \
        tma3(stg(s_) + 28672u + g_ * 4096u, &mWih1, (CK) * 64, g_ * HID + jb, 0, mbF(s_)); \
        tma3(stg(s_) + 40960u + g_ * 4096u, &mWhh,  (CK) * 64, g_ * HID + jb, 1, mbF(s_)); \
    } \
} while (0)
// A issue: no empty wait (ISSW holds the stage), posts A tx (16384 B).
#define ISSA(X, CK) do { \
    unsigned s_ = (unsigned)(X) & 3; \
    MB_EXPECT(mbF(s_), 16384u); \
    tma3(stg(s_),         &mH0, (CK) * 64, m0, k & 1, mbF(s_)); \
    tma3(stg(s_) + 8192u, &mH1, (CK) * 64, m0, (k + 1) & 1, mbF(s_)); \
} while (0)

    // prime W for tick 0, chunks 0..2
    if (tid == 0) { ISSW(0, 0); ISSW(1, 1); ISSW(2, 2); }

    int xb = 0;
    for (int k = 0; k <= TT; k++) {
        float cA[3][4], cGi[3][4], cGh[3][4];
#pragma unroll
        for (int g = 0; g < 3; g++)
#pragma unroll
            for (int q = 0; q < 4; q++) { cA[g][q] = 0.f; cGi[g][q] = 0.f; cGh[g][q] = 0.f; }

        // A loads for the pre-issued stages (post-barrier, h state ready)
        if (tid == 0) { ISSA(xb, 0); ISSA(xb + 1, 1); ISSA(xb + 2, 2); }
        for (int ck = 0; ck < 16; ck++) {
            const int x = xb + ck;
            const unsigned s = (unsigned)x & 3;
            if (tid == 0 && ck < 13) { ISSW(x + 3, ck + 3); ISSA(x + 3, ck + 3); }
            MB_WAIT(mbF(s), ((unsigned)x >> 2) & 1u);
            const unsigned sa0 = stg(s), sa1 = stg(s) + 8192u, sw = stg(s) + 16384u;
#pragma unroll
            for (int ks = 0; ks < 4; ks++) {
                const unsigned kb = ks * 32 + hiA;
                unsigned f0[4], f1[4];
                ldsm4u(f0, sa0 + swz(rA + kb));
                ldsm4u(f1, sa1 + swz(rA + kb));
                const unsigned kbb = swz(rB + ks * 32 + hiB);
#pragma unroll
                for (int g = 0; g < 3; g++) {
                    unsigned b0[2], b1[2], b2[2];
                    ldsm2u(b0, sw + g * 4096u + kbb);            // Whh0
                    ldsm2u(b1, sw + 12288u + g * 4096u + kbb);   // Wih1
                    ldsm2u(b2, sw + 24576u + g * 4096u + kbb);   // Whh1
                    mmah(cA[g],  f0, b0);
                    mmah(cGi[g], f0, b1);
                    mmah(cGh[g], f1, b2);
                }
            }
            if (lane == 0) MB_ARRIVE(mbE(s));
        }
        xb += 16;

        // pre-issue next tick's W (k-independent; overlaps epilogue + barrier)
        if (tid == 0 && k < TT) { ISSW(xb, 0); ISSW(xb + 1, 1); ISSW(xb + 2, 2); }

        // ---- epilogue A: fuse layer0 -> h0(k) ----
        if (k < TT) {
#pragma unroll
            for (int ci2 = 0; ci2 < 2; ci2++) {
                int m = m0 + warpM * 16 + g8 + ci2 * 8;
                int tok = (k == 0) ? 0 : tgt[m * TT + k - 1];
                const float* grow = g_G0 + (size_t)tok * H3;
#pragma unroll
                for (int e = 0; e < 2; e++) {
                    int j = jb + warpJ * 8 + t4 * 2 + e;
                    int ci = ci2 * 2 + e;
                    float r = sigm(grow[j] + cA[0][ci] + bh0[j]);
                    float z = sigm(grow[HID + j] + cA[1][ci] + bh0[HID + j]);
                    float n = tanhf(grow[2 * HID + j] + r * (cA[2][ci] + bh0[2 * HID + j]));
                    float hn = (1.0f - z) * n + z * hA[ci];
                    hA[ci] = hn;
                    g_h0h[(k + 1) & 1][m * HID + j] = __float2half_rn(hn);
                    if (k == TT - 1) g_h0[0][m * HID + j] = hn;
                }
            }
        }
        // ---- epilogue B: fuse layer1 -> h1(k-1) ----
        if (k > 0) {
#pragma unroll
            for (int ci2 = 0; ci2 < 2; ci2++) {
                int m = m0 + warpM * 16 + g8 + ci2 * 8;
#pragma unroll
                for (int e = 0; e < 2; e++) {
                    int j = jb + warpJ * 8 + t4 * 2 + e;
                    int ci = ci2 * 2 + e;
                    float r = sigm(cGi[0][ci] + bi1[j] + cGh[0][ci] + bh1[j]);
                    float z = sigm(cGi[1][ci] + bi1[HID + j] + cGh[1][ci] + bh1[HID + j]);
                    float n = tanhf(cGi[2][ci] + bi1[2 * HID + j]
                                    + r * (cGh[2][ci] + bh1[2 * HID + j]));
                    float hn = (1.0f - z) * n + z * hB[ci];
                    hB[ci] = hn;
                    __half hnh = __float2half_rn(hn);
                    g_h1h[k & 1][m * HID + j] = hnh;
                    g_Hbufh[(size_t)(k - 1) * BATCH * HID + (size_t)m * HID + j] = hnh;
                    if (k == TT) g_h1[0][m * HID + j] = hn;
                }
            }
        }
        gbarrier_grp(grp);
    }
}

// ---------------- deferred fp16 output projection ----------------
__global__ __launch_bounds__(256) void k_logits16(const float* __restrict__ bo, float* __restrict__ out) {
    __shared__ __align__(16) __half sA[2][128 * 40];
    __shared__ __align__(16) __half sB[2][64 * 40];
    const int tid = threadIdx.x, lane = tid & 31, wid = tid >> 5;
    const int t4 = lane & 3, g8 = lane >> 2;
    const int warpM = wid & 3, warpN = wid >> 2;
    const int m0 = blockIdx.y * 128, n0 = blockIdx.x * 64;
    const int arow = tid >> 2, aseg = (tid & 3) * 8;
    const __half* Ah = g_Hbufh;
    const int l15 = lane & 15;
    const int aR = l15, aKo = (lane >> 4) * 8;
    const int bR = (lane >> 4) * 8 + (lane & 7), bKo = ((lane >> 3) & 1) * 8;
    float c[2][4][4];
#pragma unroll
    for (int i = 0; i < 2; i++)
#pragma unroll
        for (int j = 0; j < 4; j++)
#pragma unroll
            for (int q = 0; q < 4; q++) c[i][j][q] = 0.f;
#define LOADL(BF, KK) do { \
    cpa16(&sA[BF][arow * 40 + aseg], Ah + (size_t)(m0 + arow) * HID + (KK) + aseg); \
    cpa16(&sA[BF][(arow + 64) * 40 + aseg], Ah + (size_t)(m0 + arow + 64) * HID + (KK) + aseg); \
    cpa16(&sB[BF][arow * 40 + aseg], g_Wo_h + (size_t)(n0 + arow) * HID + (KK) + aseg); } while (0)
    LOADL(0, 0); cpcommit();
    for (int ck = 0; ck < 32; ck++) {
        int buf = ck & 1;
        if (ck < 31) { LOADL(buf ^ 1, (ck + 1) * 32); cpcommit(); cpwait1(); }
        else cpwait0();
        __syncthreads();
#pragma unroll
        for (int ks = 0; ks < 2; ks++) {
            unsigned a[2][4], b4[2][4];
#pragma unroll
            for (int mt = 0; mt < 2; mt++)
                ldsm4h(a[mt], &sA[buf][(warpM * 32 + mt * 16 + aR) * 40 + ks * 16 + aKo]);
#pragma unroll
            for (int pr = 0; pr < 2; pr++)
                ldsm4h(b4[pr], &sB[buf][(warpN * 32 + pr * 16 + bR) * 40 + ks * 16 + bKo]);
#pragma unroll
            for (int pr = 0; pr < 2; pr++)
#pragma unroll
                for (int h2 = 0; h2 < 2; h2++) {
                    unsigned b[2] = { b4[pr][h2 * 2], b4[pr][h2 * 2 + 1] };
                    int nt = pr * 2 + h2;
                    mmah(c[0][nt], a[0], b);
                    mmah(c[1][nt], a[1], b);
                }
        }
        __syncthreads();
    }
#pragma unroll
    for (int mt = 0; mt < 2; mt++)
#pragma unroll
        for (int nt = 0; nt < 4; nt++)
#pragma unroll
            for (int ci = 0; ci < 4; ci++) {
                int m = m0 + warpM * 32 + mt * 16 + g8 + ((ci & 2) ? 8 : 0);
                int n = n0 + warpN * 32 + nt * 8 + t4 * 2 + (ci & 1);
                int bb = m & (BATCH - 1), tt = m >> 8;
                out[((size_t)bb * TT + tt) * VOC + n] = c[mt][nt][ci] + bo[n];
            }
}

__global__ __launch_bounds__(128) void k_lsm(float* out) {
    float* p = out + (size_t)blockIdx.x * VOC;
    const int tid = threadIdx.x, lane = tid & 31, wid = tid >> 5;
    __shared__ float smx[4], ssm[4];
    float v[4];
#pragma unroll
    for (int i = 0; i < 4; i++) v[i] = p[tid + 128 * i];
    float mx = fmaxf(fmaxf(v[0], v[1]), fmaxf(v[2], v[3]));
#pragma unroll
    for (int o = 16; o; o >>= 1) mx = fmaxf(mx, __shfl_xor_sync(0xffffffffu, mx, o));
    if (lane == 0) smx[wid] = mx;
    __syncthreads();
    mx = fmaxf(fmaxf(smx[0], smx[1]), fmaxf(smx[2], smx[3]));
    float s = 0.f;
#pragma unroll
    for (int i = 0; i < 4; i++) s += __expf(v[i] - mx);
#pragma unroll
    for (int o = 16; o; o >>= 1) s += __shfl_xor_sync(0xffffffffu, s, o);
    if (lane == 0) ssm[wid] = s;
    __syncthreads();
    s = ssm[0] + ssm[1] + ssm[2] + ssm[3];
    float lse = mx + logf(s);
#pragma unroll
    for (int i = 0; i < 4; i++) p[tid + 128 * i] = v[i] - lse;
}

__global__ __launch_bounds__(512) void k_hfinal(float* outh) {
    int i = blockIdx.x * blockDim.x + threadIdx.x;
    if (i < BATCH * HID) outh[i] = g_h0[0][i];
    else outh[i] = g_h1[0][i - BATCH * HID];
}

// ---------------- host: tensormap creation ----------------
typedef CUresult (*PFN_tmap)(CUtensorMap*, CUtensorMapDataType, cuuint32_t, void*,
                             const cuuint64_t*, const cuuint64_t*, const cuuint32_t*, const cuuint32_t*,
                             CUtensorMapInterleave, CUtensorMapSwizzle, CUtensorMapL2promotion,
                             CUtensorMapFloatOOBfill);

static void make_map(PFN_tmap enc, CUtensorMap* m, void* base,
                     unsigned d0, unsigned d1, unsigned d2, unsigned box0, unsigned box1) {
    cuuint64_t dims[3]    = { d0, d1, d2 };
    cuuint64_t strides[2] = { (cuuint64_t)d0 * 2, (cuuint64_t)d0 * 2 * d1 };
    cuuint32_t box[3]     = { box0, box1, 1 };
    cuuint32_t es[3]      = { 1, 1, 1 };
    enc(m, CU_TENSOR_MAP_DATA_TYPE_FLOAT16, 3, base, dims, strides, box, es,
        CU_TENSOR_MAP_INTERLEAVE_NONE, CU_TENSOR_MAP_SWIZZLE_128B,
        CU_TENSOR_MAP_L2_PROMOTION_L2_128B, CU_TENSOR_MAP_FLOAT_OOB_FILL_NONE);
}

// ---------------- launch ----------------
extern "C" void kernel_launch(void* const* d_in, const int* in_sizes, int n_in,
                              void* d_out, int out_size) {
    (void)in_sizes; (void)n_in; (void)out_size;
    const float* fp   = (const float*)d_in[1];
    const int*   tgt  = (const int*)d_in[2];
    const float* emb  = (const float*)d_in[3];
    const float* Wc   = (const float*)d_in[4];
    const float* bc   = (const float*)d_in[5];
    const float* W_ih = (const float*)d_in[6];
    const float* W_hh = (const float*)d_in[7];
    const float* b_ih = (const float*)d_in[8];
    const float* b_hh = (const float*)d_in[9];
    const float* Wo   = (const float*)d_in[10];
    const float* bo   = (const float*)d_in[11];
    float* out = (float*)d_out;

    void* fnp = nullptr;
    cudaDriverEntryPointQueryResult qr;
    cudaGetDriverEntryPointByVersion("cuTensorMapEncodeTiled", &fnp, 12000, cudaEnableDefault, &qr);
    PFN_tmap enc = (PFN_tmap)fnp;

    void *pWhh = nullptr, *pWih1 = nullptr, *pH0 = nullptr, *pH1 = nullptr;
    cudaGetSymbolAddress(&pWhh, g_Whh_h);
    cudaGetSymbolAddress(&pWih1, g_Wih1_h);
    cudaGetSymbolAddress(&pH0, g_h0h);
    cudaGetSymbolAddress(&pH1, g_h1h);

    CUtensorMap mWhh, mWih1, mH0, mH1;
    make_map(enc, &mWhh,  pWhh,  HID, H3, 2, 64, 32);
    make_map(enc, &mWih1, pWih1, HID, H3, 1, 64, 32);
    make_map(enc, &mH0,   pH0,   HID, BATCH, 2, 64, 64);
    make_map(enc, &mH1,   pH1,   HID, BATCH, 2, 64, 64);

    cudaFuncSetAttribute(k_loop, cudaFuncAttributeMaxDynamicSharedMemorySize, KLOOP_SMEM);

    k_init_h0<<<dim3(16, 4), 256>>>(fp, Wc, bc);
    k_init_G0<<<dim3(48, 8), 256>>>(emb, W_ih, b_ih);
    k_convW<<<1024, 256>>>(W_hh, W_ih, Wo);
    k_loop<<<NB, 512, KLOOP_SMEM>>>(tgt, b_ih, b_hh, mWhh, mWih1, mH0, mH1);
    k_logits16<<<dim3(8, 512), 256>>>(bo, out);
    k_lsm<<<65536, 128>>>(out);
    k_hfinal<<<1024, 512>>>(out + (size_t)BATCH * TT * VOC);
}

// round 15
// speedup vs baseline: 1.1098x; 1.1098x over previous
#include <cuda_runtime.h>
#include <cuda_fp16.h>
#include <cuda.h>
#include <math.h>

#define BATCH 256
#define HID   1024
#define H3    3072
#define VOC   512
#define TT    256
#define FPD   2048
#define WH    (H3 * HID)
#define NB    128

// ---------------- device scratch ----------------
__device__ __align__(256) float  g_h0[2][BATCH * HID];
__device__ __align__(256) float  g_h1[2][BATCH * HID];
__device__ __align__(256) __half g_h0h[2][BATCH * HID];
__device__ __align__(256) __half g_h1h[2][BATCH * HID];
__device__ __align__(256) float  g_G0[VOC * H3];
__device__ __align__(256) __half g_Whh_h[2][WH];
__device__ __align__(256) __half g_Wih1_h[WH];
__device__ __align__(256) __half g_Wo_h[VOC * HID];
__device__ __align__(256) __half g_Hbufh[(size_t)TT * BATCH * HID];
__device__ unsigned g_bar_cnt4[4] = {0, 0, 0, 0};
__device__ unsigned g_bar_gen4[4] = {0, 0, 0, 0};

// ---------------- helpers ----------------
__device__ __forceinline__ unsigned f2tf(float f) {
    unsigned u; asm("cvt.rna.tf32.f32 %0, %1;" : "=r"(u) : "f"(f)); return u;
}
__device__ __forceinline__ void mma8(float c[4], const unsigned a[4], const unsigned b[2]) {
    asm volatile("mma.sync.aligned.m16n8k8.row.col.f32.tf32.tf32.f32 "
                 "{%0,%1,%2,%3},{%4,%5,%6,%7},{%8,%9},{%0,%1,%2,%3};"
                 : "+f"(c[0]), "+f"(c[1]), "+f"(c[2]), "+f"(c[3])
                 : "r"(a[0]), "r"(a[1]), "r"(a[2]), "r"(a[3]), "r"(b[0]), "r"(b[1]));
}
__device__ __forceinline__ void mmah(float c[4], const unsigned a[4], const unsigned b[2]) {
    asm volatile("mma.sync.aligned.m16n8k16.row.col.f32.f16.f16.f32 "
                 "{%0,%1,%2,%3},{%4,%5,%6,%7},{%8,%9},{%0,%1,%2,%3};"
                 : "+f"(c[0]), "+f"(c[1]), "+f"(c[2]), "+f"(c[3])
                 : "r"(a[0]), "r"(a[1]), "r"(a[2]), "r"(a[3]), "r"(b[0]), "r"(b[1]));
}
__device__ __forceinline__ void ldsm4u(unsigned r[4], unsigned a) {
    asm volatile("ldmatrix.sync.aligned.m8n8.x4.shared.b16 {%0,%1,%2,%3},[%4];"
                 : "=r"(r[0]), "=r"(r[1]), "=r"(r[2]), "=r"(r[3]) : "r"(a));
}
__device__ __forceinline__ void ldsm2u(unsigned r[2], unsigned a) {
    asm volatile("ldmatrix.sync.aligned.m8n8.x2.shared.b16 {%0,%1},[%2];"
                 : "=r"(r[0]), "=r"(r[1]) : "r"(a));
}
__device__ __forceinline__ void ldsm4h(unsigned r[4], const __half* p) {
    ldsm4u(r, (unsigned)__cvta_generic_to_shared(p));
}
__device__ __forceinline__ float tanhfast(float x) {
    float y; asm("tanh.approx.f32 %0, %1;" : "=f"(y) : "f"(x)); return y;
}
__device__ __forceinline__ float sigmfast(float x) {
    return fmaf(0.5f, tanhfast(0.5f * x), 0.5f);
}
__device__ __forceinline__ float sigm(float x) { return 1.0f / (1.0f + __expf(-x)); }
__device__ __forceinline__ void cpa16(const __half* dst, const __half* src) {
    unsigned d = (unsigned)__cvta_generic_to_shared(dst);
    asm volatile("cp.async.cg.shared.global [%0], [%1], 16;" :: "r"(d), "l"(src));
}
__device__ __forceinline__ void cpcommit() { asm volatile("cp.async.commit_group;"); }
__device__ __forceinline__ void cpwait1()  { asm volatile("cp.async.wait_group 1;"); }
__device__ __forceinline__ void cpwait0()  { asm volatile("cp.async.wait_group 0;"); }
__device__ __forceinline__ unsigned swz(unsigned o) { return o ^ ((o >> 3) & 0x70); }

#define MB_INIT(addr, cnt) asm volatile("mbarrier.init.shared.b64 [%0], %1;" :: "r"(addr), "r"(cnt) : "memory")
#define MB_EXPECT(addr, bytes) asm volatile("mbarrier.arrive.expect_tx.shared.b64 _, [%0], %1;" :: "r"(addr), "r"(bytes) : "memory")
#define MB_ARRIVE(addr) asm volatile("mbarrier.arrive.shared.b64 _, [%0];" :: "r"(addr) : "memory")
#define MB_WAIT(addr, par) do { \
    unsigned _m = (addr); unsigned _p = (par); unsigned _d; \
    asm volatile("{\n\t.reg .pred p;\n\tmbarrier.try_wait.parity.acquire.cta.shared::cta.b64 p, [%1], %2;\n\tselp.b32 %0, 1, 0, p;\n\t}" \
        : "=r"(_d) : "r"(_m), "r"(_p) : "memory"); \
    if (!_d) { \
        asm volatile("{\n\t.reg .pred P1;\n\tWL_%=:\n\tmbarrier.try_wait.parity.acquire.cta.shared::cta.b64 P1, [%0], %1, 0x989680;\n\t@P1 bra.uni WD_%=;\n\tbra.uni WL_%=;\n\tWD_%=:\n\t}" \
            :: "r"(_m), "r"(_p) : "memory"); \
    } \
} while (0)

__device__ __forceinline__ void tma3(unsigned dst, const CUtensorMap* m, int x, int y, int z, unsigned mb) {
    asm volatile("cp.async.bulk.tensor.3d.shared::cta.global.tile.mbarrier::complete_tx::bytes "
                 "[%0], [%1, {%2,%3,%4}], [%5];"
                 :: "r"(dst), "l"(m), "r"(x), "r"(y), "r"(z), "r"(mb) : "memory");
}

// 32-CTA m-group barrier (groups are independent)
__device__ __forceinline__ void gbarrier_grp(int grp) {
    __threadfence();
    __syncthreads();
    if (threadIdx.x == 0) {
        unsigned gen = *((volatile unsigned*)&g_bar_gen4[grp]);
        if (atomicAdd(&g_bar_cnt4[grp], 1u) == 31u) {
            g_bar_cnt4[grp] = 0;
            __threadfence();
            atomicAdd(&g_bar_gen4[grp], 1u);
        } else {
            while (*((volatile unsigned*)&g_bar_gen4[grp]) == gen) { __nanosleep(16); }
        }
    }
    __syncthreads();
}

// ---------------- tf32 64x64 GEMM (init kernels only) ----------------
__device__ __forceinline__ void gemm64x64(const float* A, int lda, const float* W, int ldw,
                                          int K, int m0, int n0, int reluA,
                                          unsigned* As, unsigned* Bs, float c[2][2][4]) {
    const int tid = threadIdx.x, lane = tid & 31, wid = tid >> 5;
    const int g = lane >> 2, t4 = lane & 3;
    const int warpM = wid >> 2, warpN = wid & 3;
    for (int kk = 0; kk < K; kk += 32) {
#pragma unroll
        for (int p = 0; p < 2; p++) {
            int r = p * 32 + (tid >> 3), c4 = (tid & 7) * 4;
            float4 v = *(const float4*)(A + (size_t)(m0 + r) * lda + kk + c4);
            if (reluA) { v.x = fmaxf(v.x, 0.f); v.y = fmaxf(v.y, 0.f); v.z = fmaxf(v.z, 0.f); v.w = fmaxf(v.w, 0.f); }
            unsigned* d = As + r * 36 + c4;
            d[0] = f2tf(v.x); d[1] = f2tf(v.y); d[2] = f2tf(v.z); d[3] = f2tf(v.w);
            float4 w = *(const float4*)(W + (size_t)(n0 + r) * ldw + kk + c4);
            unsigned* e = Bs + r * 36 + c4;
            e[0] = f2tf(w.x); e[1] = f2tf(w.y); e[2] = f2tf(w.z); e[3] = f2tf(w.w);
        }
        __syncthreads();
#pragma unroll
        for (int ks = 0; ks < 4; ks++) {
            int kb = ks * 8;
            unsigned a[2][4], b[2][2];
#pragma unroll
            for (int mt = 0; mt < 2; mt++) {
                int row = warpM * 32 + mt * 16 + g;
                a[mt][0] = As[row * 36 + kb + t4];
                a[mt][1] = As[(row + 8) * 36 + kb + t4];
                a[mt][2] = As[row * 36 + kb + t4 + 4];
                a[mt][3] = As[(row + 8) * 36 + kb + t4 + 4];
            }
#pragma unroll
            for (int nt = 0; nt < 2; nt++) {
                int nr = warpN * 16 + nt * 8 + g;
                b[nt][0] = Bs[nr * 36 + kb + t4];
                b[nt][1] = Bs[nr * 36 + kb + t4 + 4];
            }
#pragma unroll
            for (int mt = 0; mt < 2; mt++)
#pragma unroll
                for (int nt = 0; nt < 2; nt++) mma8(c[mt][nt], a[mt], b[nt]);
        }
        __syncthreads();
    }
}

__global__ __launch_bounds__(256) void k_init_h0(const float* fp, const float* Wc, const float* bc) {
    __shared__ unsigned As[64 * 36], Bs[64 * 36];
    float c[2][2][4] = {};
    int n0 = blockIdx.x * 64, m0 = blockIdx.y * 64;
    gemm64x64(fp, FPD, Wc, FPD, FPD, m0, n0, 0, As, Bs, c);
    const int tid = threadIdx.x, lane = tid & 31, wid = tid >> 5;
    const int g = lane >> 2, t4 = lane & 3;
    const int warpM = wid >> 2, warpN = wid & 3;
#pragma unroll
    for (int mt = 0; mt < 2; mt++)
#pragma unroll
        for (int nt = 0; nt < 2; nt++)
#pragma unroll
            for (int ci = 0; ci < 4; ci++) {
                int m = m0 + warpM * 32 + mt * 16 + g + ((ci & 2) ? 8 : 0);
                int n = n0 + warpN * 16 + nt * 8 + t4 * 2 + (ci & 1);
                float v = fmaxf(c[mt][nt][ci] + bc[n], 0.f);
                g_h0[0][m * HID + n] = v;
                g_h1[0][m * HID + n] = v;
                __half vh = __float2half_rn(v);
                g_h0h[0][m * HID + n] = vh;
                g_h1h[0][m * HID + n] = vh;
                g_h1h[1][m * HID + n] = vh;
            }
}

__global__ __launch_bounds__(256) void k_init_G0(const float* emb, const float* Wih, const float* bih) {
    __shared__ unsigned As[64 * 36], Bs[64 * 36];
    float c[2][2][4] = {};
    int n0 = blockIdx.x * 64, m0 = blockIdx.y * 64;
    gemm64x64(emb, HID, Wih, HID, HID, m0, n0, 1, As, Bs, c);
    const int tid = threadIdx.x, lane = tid & 31, wid = tid >> 5;
    const int g = lane >> 2, t4 = lane & 3;
    const int warpM = wid >> 2, warpN = wid & 3;
#pragma unroll
    for (int mt = 0; mt < 2; mt++)
#pragma unroll
        for (int nt = 0; nt < 2; nt++)
#pragma unroll
            for (int ci = 0; ci < 4; ci++) {
                int m = m0 + warpM * 32 + mt * 16 + g + ((ci & 2) ? 8 : 0);
                int n = n0 + warpN * 16 + nt * 8 + t4 * 2 + (ci & 1);
                g_G0[m * H3 + n] = c[mt][nt][ci] + bih[n];
            }
}

__global__ __launch_bounds__(256) void k_convW(const float* Whh, const float* Wih, const float* Wo) {
    size_t i = (size_t)blockIdx.x * blockDim.x + threadIdx.x;
    size_t stride = (size_t)gridDim.x * blockDim.x;
    __half* whh = &g_Whh_h[0][0];
    for (size_t k = i; k < 2 * (size_t)WH; k += stride) whh[k] = __float2half_rn(Whh[k]);
    for (size_t k = i; k < (size_t)WH; k += stride) g_Wih1_h[k] = __float2half_rn(Wih[WH + k]);
    for (size_t k = i; k < (size_t)VOC * HID; k += stride) g_Wo_h[k] = __float2half_rn(Wo[k]);
}

// ---------------- persistent recurrent kernel (v13: R12 + epilogue-tail cuts) ----------------
// Tick k (k=0..TT): A(k): gh0 = h0(k-1)@Whh0 -> h0(k)   [skip at k=TT]
//                   B(k-1): gh1 = h1(k-2)@Whh1, gi1 = h0(k-1)@Wih1, fuse -> h1(k-1) [skip at k=0]
// CTA tile: 64m x (3 gates x 32j); 4 m-tiles x 32 j-tiles = 128 CTAs. 16 warps = 4M x 4J, warp 16m x 8j.
// Biases pre-folded into accumulator init; tokens prefetched; tanh.approx transcendentals.
#define STG_BYTES 53248   // h0 8K + h1 8K + 9 W boxes x 4K
#define NSTG 4
#define KLOOP_SMEM (NSTG * STG_BYTES)

__global__ __launch_bounds__(512, 1)
void k_loop(const int* __restrict__ tgt, const float* __restrict__ b_ih, const float* __restrict__ b_hh,
            const __grid_constant__ CUtensorMap mWhh, const __grid_constant__ CUtensorMap mWih1,
            const __grid_constant__ CUtensorMap mH0,  const __grid_constant__ CUtensorMap mH1)
{
    extern __shared__ __align__(1024) char dynsm[];
    __shared__ __align__(8) unsigned long long s_mbar[2 * NSTG];
    const unsigned smb = (unsigned)__cvta_generic_to_shared(dynsm);
    const unsigned mbb = (unsigned)__cvta_generic_to_shared(s_mbar);
#define mbF(s)  (mbb + (s) * 8)
#define mbE(s)  (mbb + NSTG * 8 + (s) * 8)
#define stg(s)  (smb + (s) * STG_BYTES)

    const int tid = threadIdx.x, lane = tid & 31, wid = tid >> 5;
    const int g8 = lane >> 2, t4 = lane & 3;
    const int warpM = wid & 3, warpJ = wid >> 2;      // 4M x 4J
    const int bid = blockIdx.x;
    const int grp = bid >> 5;                          // m-group (32 CTAs share m0)
    const int m0 = grp * 64;
    const int jb = (bid & 31) * 32;
    const float* bh0 = b_hh;
    const float* bh1 = b_hh + H3;
    const float* bi1 = b_ih + H3;

    if (tid == 0) {
#pragma unroll
        for (int s = 0; s < NSTG; s++) { MB_INIT(mbF(s), 1); MB_INIT(mbE(s), 16); }
    }
    __syncthreads();

    const int jA = jb + warpJ * 8 + t4 * 2;            // e=0 column; e=1 is jA+1
    const int mA = m0 + warpM * 16 + g8;               // ci2=0 row; ci2=1 is mA+8

    // register-resident hidden state for this thread's epilogue positions
    float hA[4], hB[4];
#pragma unroll
    for (int ci2 = 0; ci2 < 2; ci2++)
#pragma unroll
        for (int e = 0; e < 2; e++) {
            hA[ci2 * 2 + e] = g_h0[0][(mA + ci2 * 8) * HID + jA + e];
            hB[ci2 * 2 + e] = g_h1[0][(mA + ci2 * 8) * HID + jA + e];
        }

    // ldmatrix lane addressing (offsets within swizzled 128B-row boxes)
    const int l15 = lane & 15;
    const unsigned hiA = (lane >> 4) * 16;
    const unsigned rA  = (unsigned)(warpM * 16 + l15) * 128;        // 16m warp tile
    const unsigned rB  = (unsigned)(warpJ * 8 + (l15 & 7)) * 128;
    const unsigned hiB = ((l15 >> 3) & 1) * 16;

#define ISSUE(X, CK) do { \
    unsigned s_ = (unsigned)(X) & 3; \
    MB_WAIT(mbE(s_), ((((unsigned)(X)) >> 2) & 1u) ^ 1u); \
    MB_EXPECT(mbF(s_), 53248u); \
    tma3(stg(s_),         &mH0, (CK) * 64, m0, k & 1, mbF(s_)); \
    tma3(stg(s_) + 8192u, &mH1, (CK) * 64, m0, (k + 1) & 1, mbF(s_)); \
    _Pragma("unroll") for (int g_ = 0; g_ < 3; g_++) { \
        tma3(stg(s_) + 16384u + g_ * 4096u, &mWhh,  (CK) * 64, g_ * HID + jb, 0, mbF(s_)); \
        tma3(stg(s_) + 28672u + g_ * 4096u, &mWih1, (CK) * 64, g_ * HID + jb, 0, mbF(s_)); \
        tma3(stg(s_) + 40960u + g_ * 4096u, &mWhh,  (CK) * 64, g_ * HID + jb, 1, mbF(s_)); \
    } \
} while (0)

    int xb = 0;
    for (int k = 0; k <= TT; k++) {
        // bias-initialized accumulators (loads issued at tick start, overlapped with TMA wait)
        float cA[3][4], cGi[3][4], cGh[3][4];
#pragma unroll
        for (int g = 0; g < 3; g++) {
            float a0 = bh0[g * HID + jA], a1 = bh0[g * HID + jA + 1];
            float i0 = bi1[g * HID + jA], i1 = bi1[g * HID + jA + 1];
            float h0b = bh1[g * HID + jA], h1b = bh1[g * HID + jA + 1];
            cA[g][0] = a0;  cA[g][1] = a1;  cA[g][2] = a0;  cA[g][3] = a1;
            cGi[g][0] = i0; cGi[g][1] = i1; cGi[g][2] = i0; cGi[g][3] = i1;
            cGh[g][0] = h0b; cGh[g][1] = h1b; cGh[g][2] = h0b; cGh[g][3] = h1b;
        }
        // token prefetch (known at tick start; removes one L2 trip from epilogue chain)
        int tok0 = 0, tok1 = 0;
        if (k > 0 && k < TT) {
            tok0 = tgt[mA * TT + k - 1];
            tok1 = tgt[(mA + 8) * TT + k - 1];
        }

        if (tid == 0) { ISSUE(xb, 0); ISSUE(xb + 1, 1); ISSUE(xb + 2, 2); }
        for (int ck = 0; ck < 16; ck++) {
            const int x = xb + ck;
            const unsigned s = (unsigned)x & 3;
            if (tid == 0 && ck < 13) ISSUE(x + 3, ck + 3);
            MB_WAIT(mbF(s), ((unsigned)x >> 2) & 1u);
            const unsigned sa0 = stg(s), sa1 = stg(s) + 8192u, sw = stg(s) + 16384u;
#pragma unroll
            for (int ks = 0; ks < 4; ks++) {
                const unsigned kb = ks * 32 + hiA;
                unsigned f0[4], f1[4];
                ldsm4u(f0, sa0 + swz(rA + kb));
                ldsm4u(f1, sa1 + swz(rA + kb));
                const unsigned kbb = swz(rB + ks * 32 + hiB);
#pragma unroll
                for (int g = 0; g < 3; g++) {
                    unsigned b0[2], b1[2], b2[2];
                    ldsm2u(b0, sw + g * 4096u + kbb);            // Whh0
                    ldsm2u(b1, sw + 12288u + g * 4096u + kbb);   // Wih1
                    ldsm2u(b2, sw + 24576u + g * 4096u + kbb);   // Whh1
                    mmah(cA[g],  f0, b0);
                    mmah(cGi[g], f0, b1);
                    mmah(cGh[g], f1, b2);
                }
            }
            if (lane == 0) MB_ARRIVE(mbE(s));
        }
        xb += 16;

        // ---- epilogue A: fuse layer0 -> h0(k) ----
        if (k < TT) {
#pragma unroll
            for (int ci2 = 0; ci2 < 2; ci2++) {
                int m = mA + ci2 * 8;
                const float* grow = g_G0 + (size_t)(ci2 ? tok1 : tok0) * H3;
#pragma unroll
                for (int e = 0; e < 2; e++) {
                    int j = jA + e;
                    int ci = ci2 * 2 + e;
                    float r = sigmfast(grow[j] + cA[0][ci]);
                    float z = sigmfast(grow[HID + j] + cA[1][ci]);
                    float n = tanhfast(grow[2 * HID + j] + r * cA[2][ci]);
                    float hn = (1.0f - z) * n + z * hA[ci];
                    hA[ci] = hn;
                    g_h0h[(k + 1) & 1][m * HID + j] = __float2half_rn(hn);
                    if (k == TT - 1) g_h0[0][m * HID + j] = hn;
                }
            }
        }
        // ---- epilogue B: fuse layer1 -> h1(k-1) ----
        if (k > 0) {
#pragma unroll
            for (int ci2 = 0; ci2 < 2; ci2++) {
                int m = mA + ci2 * 8;
#pragma unroll
                for (int e = 0; e < 2; e++) {
                    int j = jA + e;
                    int ci = ci2 * 2 + e;
                    float r = sigmfast(cGi[0][ci] + cGh[0][ci]);
                    float z = sigmfast(cGi[1][ci] + cGh[1][ci]);
                    float n = tanhfast(cGi[2][ci] + r * cGh[2][ci]);
                    float hn = (1.0f - z) * n + z * hB[ci];
                    hB[ci] = hn;
                    __half hnh = __float2half_rn(hn);
                    g_h1h[k & 1][m * HID + j] = hnh;
                    g_Hbufh[(size_t)(k - 1) * BATCH * HID + (size_t)m * HID + j] = hnh;
                    if (k == TT) g_h1[0][m * HID + j] = hn;
                }
            }
        }
        gbarrier_grp(grp);
    }
}

// ---------------- deferred fp16 output projection ----------------
__global__ __launch_bounds__(256) void k_logits16(const float* __restrict__ bo, float* __restrict__ out) {
    __shared__ __align__(16) __half sA[2][128 * 40];
    __shared__ __align__(16) __half sB[2][64 * 40];
    const int tid = threadIdx.x, lane = tid & 31, wid = tid >> 5;
    const int t4 = lane & 3, g8 = lane >> 2;
    const int warpM = wid & 3, warpN = wid >> 2;
    const int m0 = blockIdx.y * 128, n0 = blockIdx.x * 64;
    const int arow = tid >> 2, aseg = (tid & 3) * 8;
    const __half* Ah = g_Hbufh;
    const int l15 = lane & 15;
    const int aR = l15, aKo = (lane >> 4) * 8;
    const int bR = (lane >> 4) * 8 + (lane & 7), bKo = ((lane >> 3) & 1) * 8;
    float c[2][4][4];
#pragma unroll
    for (int i = 0; i < 2; i++)
#pragma unroll
        for (int j = 0; j < 4; j++)
#pragma unroll
            for (int q = 0; q < 4; q++) c[i][j][q] = 0.f;
#define LOADL(BF, KK) do { \
    cpa16(&sA[BF][arow * 40 + aseg], Ah + (size_t)(m0 + arow) * HID + (KK) + aseg); \
    cpa16(&sA[BF][(arow + 64) * 40 + aseg], Ah + (size_t)(m0 + arow + 64) * HID + (KK) + aseg); \
    cpa16(&sB[BF][arow * 40 + aseg], g_Wo_h + (size_t)(n0 + arow) * HID + (KK) + aseg); } while (0)
    LOADL(0, 0); cpcommit();
    for (int ck = 0; ck < 32; ck++) {
        int buf = ck & 1;
        if (ck < 31) { LOADL(buf ^ 1, (ck + 1) * 32); cpcommit(); cpwait1(); }
        else cpwait0();
        __syncthreads();
#pragma unroll
        for (int ks = 0; ks < 2; ks++) {
            unsigned a[2][4], b4[2][4];
#pragma unroll
            for (int mt = 0; mt < 2; mt++)
                ldsm4h(a[mt], &sA[buf][(warpM * 32 + mt * 16 + aR) * 40 + ks * 16 + aKo]);
#pragma unroll
            for (int pr = 0; pr < 2; pr++)
                ldsm4h(b4[pr], &sB[buf][(warpN * 32 + pr * 16 + bR) * 40 + ks * 16 + bKo]);
#pragma unroll
            for (int pr = 0; pr < 2; pr++)
#pragma unroll
                for (int h2 = 0; h2 < 2; h2++) {
                    unsigned b[2] = { b4[pr][h2 * 2], b4[pr][h2 * 2 + 1] };
                    int nt = pr * 2 + h2;
                    mmah(c[0][nt], a[0], b);
                    mmah(c[1][nt], a[1], b);
                }
        }
        __syncthreads();
    }
#pragma unroll
    for (int mt = 0; mt < 2; mt++)
#pragma unroll
        for (int nt = 0; nt < 4; nt++)
#pragma unroll
            for (int ci = 0; ci < 4; ci++) {
                int m = m0 + warpM * 32 + mt * 16 + g8 + ((ci & 2) ? 8 : 0);
                int n = n0 + warpN * 32 + nt * 8 + t4 * 2 + (ci & 1);
                int bb = m & (BATCH - 1), tt = m >> 8;
                out[((size_t)bb * TT + tt) * VOC + n] = c[mt][nt][ci] + bo[n];
            }
}

__global__ __launch_bounds__(128) void k_lsm(float* out) {
    float* p = out + (size_t)blockIdx.x * VOC;
    const int tid = threadIdx.x, lane = tid & 31, wid = tid >> 5;
    __shared__ float smx[4], ssm[4];
    float v[4];
#pragma unroll
    for (int i = 0; i < 4; i++) v[i] = p[tid + 128 * i];
    float mx = fmaxf(fmaxf(v[0], v[1]), fmaxf(v[2], v[3]));
#pragma unroll
    for (int o = 16; o; o >>= 1) mx = fmaxf(mx, __shfl_xor_sync(0xffffffffu, mx, o));
    if (lane == 0) smx[wid] = mx;
    __syncthreads();
    mx = fmaxf(fmaxf(smx[0], smx[1]), fmaxf(smx[2], smx[3]));
    float s = 0.f;
#pragma unroll
    for (int i = 0; i < 4; i++) s += __expf(v[i] - mx);
#pragma unroll
    for (int o = 16; o; o >>= 1) s += __shfl_xor_sync(0xffffffffu, s, o);
    if (lane == 0) ssm[wid] = s;
    __syncthreads();
    s = ssm[0] + ssm[1] + ssm[2] + ssm[3];
    float lse = mx + logf(s);
#pragma unroll
    for (int i = 0; i < 4; i++) p[tid + 128 * i] = v[i] - lse;
}

__global__ __launch_bounds__(512) void k_hfinal(float* outh) {
    int i = blockIdx.x * blockDim.x + threadIdx.x;
    if (i < BATCH * HID) outh[i] = g_h0[0][i];
    else outh[i] = g_h1[0][i - BATCH * HID];
}

// ---------------- host: tensormap creation ----------------
typedef CUresult (*PFN_tmap)(CUtensorMap*, CUtensorMapDataType, cuuint32_t, void*,
                             const cuuint64_t*, const cuuint64_t*, const cuuint32_t*, const cuuint32_t*,
                             CUtensorMapInterleave, CUtensorMapSwizzle, CUtensorMapL2promotion,
                             CUtensorMapFloatOOBfill);

static void make_map(PFN_tmap enc, CUtensorMap* m, void* base,
                     unsigned d0, unsigned d1, unsigned d2, unsigned box0, unsigned box1) {
    cuuint64_t dims[3]    = { d0, d1, d2 };
    cuuint64_t strides[2] = { (cuuint64_t)d0 * 2, (cuuint64_t)d0 * 2 * d1 };
    cuuint32_t box[3]     = { box0, box1, 1 };
    cuuint32_t es[3]      = { 1, 1, 1 };
    enc(m, CU_TENSOR_MAP_DATA_TYPE_FLOAT16, 3, base, dims, strides, box, es,
        CU_TENSOR_MAP_INTERLEAVE_NONE, CU_TENSOR_MAP_SWIZZLE_128B,
        CU_TENSOR_MAP_L2_PROMOTION_L2_128B, CU_TENSOR_MAP_FLOAT_OOB_FILL_NONE);
}

// ---------------- launch ----------------
extern "C" void kernel_launch(void* const* d_in, const int* in_sizes, int n_in,
                              void* d_out, int out_size) {
    (void)in_sizes; (void)n_in; (void)out_size;
    const float* fp   = (const float*)d_in[1];
    const int*   tgt  = (const int*)d_in[2];
    const float* emb  = (const float*)d_in[3];
    const float* Wc   = (const float*)d_in[4];
    const float* bc   = (const float*)d_in[5];
    const float* W_ih = (const float*)d_in[6];
    const float* W_hh = (const float*)d_in[7];
    const float* b_ih = (const float*)d_in[8];
    const float* b_hh = (const float*)d_in[9];
    const float* Wo   = (const float*)d_in[10];
    const float* bo   = (const float*)d_in[11];
    float* out = (float*)d_out;

    void* fnp = nullptr;
    cudaDriverEntryPointQueryResult qr;
    cudaGetDriverEntryPointByVersion("cuTensorMapEncodeTiled", &fnp, 12000, cudaEnableDefault, &qr);
    PFN_tmap enc = (PFN_tmap)fnp;

    void *pWhh = nullptr, *pWih1 = nullptr, *pH0 = nullptr, *pH1 = nullptr;
    cudaGetSymbolAddress(&pWhh, g_Whh_h);
    cudaGetSymbolAddress(&pWih1, g_Wih1_h);
    cudaGetSymbolAddress(&pH0, g_h0h);
    cudaGetSymbolAddress(&pH1, g_h1h);

    CUtensorMap mWhh, mWih1, mH0, mH1;
    make_map(enc, &mWhh,  pWhh,  HID, H3, 2, 64, 32);
    make_map(enc, &mWih1, pWih1, HID, H3, 1, 64, 32);
    make_map(enc, &mH0,   pH0,   HID, BATCH, 2, 64, 64);
    make_map(enc, &mH1,   pH1,   HID, BATCH, 2, 64, 64);

    cudaFuncSetAttribute(k_loop, cudaFuncAttributeMaxDynamicSharedMemorySize, KLOOP_SMEM);

    k_init_h0<<<dim3(16, 4), 256>>>(fp, Wc, bc);
    k_init_G0<<<dim3(48, 8), 256>>>(emb, W_ih, b_ih);
    k_convW<<<1024, 256>>>(W_hh, W_ih, Wo);
    k_loop<<<NB, 512, KLOOP_SMEM>>>(tgt, b_ih, b_hh, mWhh, mWih1, mH0, mH1);
    k_logits16<<<dim3(8, 512), 256>>>(bo, out);
    k_lsm<<<65536, 128>>>(out);
    k_hfinal<<<1024, 512>>>(out + (size_t)BATCH * TT * VOC);
}